// round 12
// baseline (speedup 1.0000x reference)
#include <cuda_runtime.h>
#include <math.h>

#define B_  64
#define LQ  32
#define O_  128
#define LK  256
#define D_  128
#define FULLM 0xffffffffu
#define GRID_N 592

__device__ __forceinline__ bool mask_at(const void* buf, int idx, int mode) {
    if (mode == 0) return ((const int*)buf)[idx] != 0;
    if (mode == 2) return ((const float*)buf)[idx] != 0.0f;
    return ((const unsigned char*)buf)[idx] != 0;
}

// ---- f32x2 packed helpers -------------------------------------------------
__device__ __forceinline__ unsigned long long pk2(float a, float b) {
    unsigned long long r;
    asm("mov.b64 %0,{%1,%2};" : "=l"(r) : "f"(a), "f"(b));
    return r;
}
__device__ __forceinline__ void fma2(unsigned long long& d,
                                     unsigned long long a, unsigned long long b) {
    asm("fma.rn.f32x2 %0,%1,%2,%0;" : "+l"(d) : "l"(a), "l"(b));
}
__device__ __forceinline__ float2 upk2(unsigned long long v) {
    float2 r;
    asm("mov.b64 {%0,%1},%2;" : "=f"(r.x), "=f"(r.y) : "l"(v));
    return r;
}

// ---------------------------------------------------------------------------
// Grid = 592 x 256. Item = (active b, o). R11 structure plus:
//  - k chunks register double-buffered: LDG for chunk c+1 issued before the
//    compute phase of chunk c -> DRAM latency hidden behind ~1600cy compute.
//  - q operand: broadcast LDS.128 over pre-duplicated f32x2 pairs (2 d/load).
// Warp w: jhalf=w&1, i rows ihw=(w>>1)*8 .. +8; lane l owns j=jhalf*128+4l..+3.
// ---------------------------------------------------------------------------
__global__ __launch_bounds__(256, 2)
void fused_score_kernel(const float* __restrict__ q,
                        const float* __restrict__ k,
                        const void* __restrict__ q_mask,
                        const void* __restrict__ k_mask,
                        const float* __restrict__ logit_scale,
                        float* __restrict__ out) {
    const int tid = threadIdx.x;
    const int w   = tid >> 5, l = tid & 31;

    __shared__ int s_nact;
    __shared__ unsigned char s_blist[B_];
    __shared__ unsigned char s_act[B_];
    extern __shared__ float smem[];
    unsigned long long* q2 = (unsigned long long*)smem;    // 4096 u64 = 32KB dup'd q
    float* kt  = smem + 2 * LQ * D_;    // 8192 f (swizzled [d][j] chunk)
    float* ivk = kt + 32 * LK;          // 256
    float* wm  = ivk + LK;              // 256
    float* ivq = wm + LK;               // 32
    float* red = ivq + LQ;              // 64

    // ---- Phase A: dtype sniff + active flags + compact list ----
    int mode;
    {
        unsigned word = ((const unsigned*)q_mask)[l];
        unsigned bi = __ballot_sync(FULLM, word <= 1u);
        unsigned bf = __ballot_sync(FULLM, word == 0u || word == 0x3F800000u);
        mode = (bi == FULLM) ? 0 : (bf == FULLM) ? 2 : 1;
    }
    {
        int bb = tid >> 2, sub = tid & 3;
        int any = 0;
        #pragma unroll
        for (int e = 0; e < 8; e++)
            any |= mask_at(q_mask, bb * LQ + sub * 8 + e, mode) ? 1 : 0;
        any |= __shfl_xor_sync(FULLM, any, 1);
        any |= __shfl_xor_sync(FULLM, any, 2);
        if ((l & 3) == 0) s_act[bb] = (any == 0);
    }
    __syncthreads();
    if (w == 0) {
        unsigned f0 = __ballot_sync(FULLM, s_act[l] != 0);
        unsigned f1 = __ballot_sync(FULLM, s_act[32 + l] != 0);
        int n0 = __popc(f0);
        if (f0 & (1u << l)) s_blist[__popc(f0 & ((1u << l) - 1u))] = (unsigned char)l;
        if (f1 & (1u << l)) s_blist[n0 + __popc(f1 & ((1u << l) - 1u))] = (unsigned char)(32 + l);
        if (l == 0) s_nact = n0 + __popc(f1);
    }
    if (blockIdx.x < B_ && tid < O_) {
        if (!s_act[blockIdx.x]) out[blockIdx.x * O_ + tid] = 0.0f;
    }
    __syncthreads();
    const int n_items = s_nact * O_;

    const int g = tid >> 3, d4 = tid & 7;
    const int jhalf = w & 1, ihw = (w >> 1) * 8;

    for (int item = blockIdx.x; item < n_items; item += GRID_N) {
        const int b = s_blist[item >> 7];
        const int o = item & (O_ - 1);

        // ---- stage q pre-duplicated + k-mask weights ----
        {
            const float2* qg = (const float2*)(q + (size_t)b * LQ * D_);
            #pragma unroll
            for (int t = 0; t < 8; t++) {
                int idx = t * 256 + tid;
                float2 v = qg[idx];
                q2[2 * idx]     = pk2(v.x, v.x);
                q2[2 * idx + 1] = pk2(v.y, v.y);
            }
            wm[tid] = mask_at(k_mask, o * LK + tid, mode) ? 0.0f : 1.0f;
        }
        __syncthreads();
        {   // warp w: invq for rows w*4 .. w*4+3
            #pragma unroll
            for (int r = 0; r < 4; r++) {
                int row = w * 4 + r;
                float s = 0.0f;
                #pragma unroll
                for (int qd = 0; qd < 4; qd++) {
                    float2 u = upk2(q2[row * D_ + qd * 32 + l]);
                    s += u.x * u.x;
                }
                #pragma unroll
                for (int of = 16; of; of >>= 1) s += __shfl_xor_sync(FULLM, s, of);
                if (l == 0) ivq[row] = 1.0f / fmaxf(sqrtf(s), 1e-12f);
            }
        }

        unsigned long long acc[8][2];
        #pragma unroll
        for (int ii = 0; ii < 8; ii++) { acc[ii][0] = 0ull; acc[ii][1] = 0ull; }
        float ksq[8];
        #pragma unroll
        for (int t8 = 0; t8 < 8; t8++) ksq[t8] = 0.0f;

        const float4* kr4 = (const float4*)(k + (size_t)o * LK * D_);

        // prefetch chunk 0 into registers
        float4 v[8];
        #pragma unroll
        for (int t8 = 0; t8 < 8; t8++)
            v[t8] = kr4[(t8 * 32 + g) * (D_ / 4) + d4];

        #pragma unroll 1
        for (int c = 0; c < 4; c++) {
            __syncthreads();                   // previous compute done with kt
            #pragma unroll
            for (int t8 = 0; t8 < 8; t8++) {   // STS buffered chunk (swizzled)
                int j = t8 * 32 + g;
                float4 u = v[t8];
                ksq[t8] += u.x * u.x + u.y * u.y + u.z * u.z + u.w * u.w;
                int col = (((j >> 2) ^ d4) << 2) + (j & 3);
                kt[(4 * d4 + 0) * LK + col] = u.x;
                kt[(4 * d4 + 1) * LK + col] = u.y;
                kt[(4 * d4 + 2) * LK + col] = u.z;
                kt[(4 * d4 + 3) * LK + col] = u.w;
            }
            __syncthreads();

            if (c < 3) {                       // prefetch next chunk (hidden)
                #pragma unroll
                for (int t8 = 0; t8 < 8; t8++)
                    v[t8] = kr4[(t8 * 32 + g) * (D_ / 4) + (c + 1) * 8 + d4];
            }

            const unsigned long long* q2b = q2 + c * 32;
            #pragma unroll 4
            for (int d2 = 0; d2 < 16; d2++) {
                const int d0 = 2 * d2;
                unsigned long long kp00, kp01, kp10, kp11;
                {
                    int s0 = (d0 >> 2) & 7;
                    const float* r0 = kt + d0 * LK + jhalf * 128;
                    float4 a = *(const float4*)(r0 + ((l ^ s0) << 2));
                    kp00 = pk2(a.x, a.y); kp01 = pk2(a.z, a.w);
                    int s1 = ((d0 + 1) >> 2) & 7;
                    const float* r1 = kt + (d0 + 1) * LK + jhalf * 128;
                    float4 c4 = *(const float4*)(r1 + ((l ^ s1) << 2));
                    kp10 = pk2(c4.x, c4.y); kp11 = pk2(c4.z, c4.w);
                }
                #pragma unroll
                for (int ii = 0; ii < 8; ii++) {
                    // broadcast LDS.128: q dup-pairs for d0 and d0+1
                    ulonglong2 qq = *(const ulonglong2*)(q2b + (ihw + ii) * D_ + d0);
                    fma2(acc[ii][0], qq.x, kp00);
                    fma2(acc[ii][1], qq.x, kp01);
                    fma2(acc[ii][0], qq.y, kp10);
                    fma2(acc[ii][1], qq.y, kp11);
                }
            }
        }

        // ---- invk from ksq (octet reduce across d4) ----
        #pragma unroll
        for (int t8 = 0; t8 < 8; t8++) {
            float s = ksq[t8];
            s += __shfl_xor_sync(FULLM, s, 1);
            s += __shfl_xor_sync(FULLM, s, 2);
            s += __shfl_xor_sync(FULLM, s, 4);
            if (d4 == 0) ivk[t8 * 32 + g] = s;
        }
        __syncthreads();
        float myinv = 1.0f / fmaxf(sqrtf(ivk[tid]), 1e-12f);
        __syncthreads();
        ivk[tid] = myinv;
        __syncthreads();

        // ---- epilogue ----
        float4 iva = *(const float4*)(ivk + jhalf * 128 + 4 * l);
        float4 wma = *(const float4*)(wm + jhalf * 128 + 4 * l);
        #pragma unroll
        for (int ii = 0; ii < 8; ii++) {
            float a12 = 12.0f * ivq[ihw + ii];
            float2 f0 = upk2(acc[ii][0]), f1 = upk2(acc[ii][1]);
            float p = wma.x * __expf(a12 * iva.x * f0.x)
                    + wma.y * __expf(a12 * iva.y * f0.y)
                    + wma.z * __expf(a12 * iva.z * f1.x)
                    + wma.w * __expf(a12 * iva.w * f1.y);
            #pragma unroll
            for (int of = 16; of; of >>= 1) p += __shfl_xor_sync(FULLM, p, of);
            if (l == 0) red[(ihw + ii) * 2 + jhalf] = p;
        }
        __syncthreads();

        if (tid < 32) {
            float p = red[2 * tid] + red[2 * tid + 1];
            float lse = __logf(p);                    // -inf if all j masked
            #pragma unroll
            for (int of = 16; of; of >>= 1) lse += __shfl_xor_sync(FULLM, lse, of);
            if (tid == 0) {
                float s = lse * (1.0f / 12.0f);
                s = s / (sqrtf((float)(LQ * LK)) + 1e-6f);
                s *= fminf(expf(logit_scale[0]), 100.0f);
                if (!isfinite(s)) s = 0.0f;
                out[b * O_ + o] = s;
            }
        }
        __syncthreads();
    }
}

// ---------------------------------------------------------------------------
extern "C" void kernel_launch(void* const* d_in, const int* in_sizes, int n_in,
                              void* d_out, int out_size) {
    const float* q  = (const float*)d_in[0];
    const float* k  = (const float*)d_in[1];
    const void*  qm = d_in[2];
    const void*  km = d_in[3];
    const float* ls = (const float*)d_in[4];
    float* out = (float*)d_out;

    const int smem_bytes =
        (2 * LQ * D_ + 32 * LK + LK + LK + LQ + 64) * (int)sizeof(float); // ~68KB
    cudaFuncSetAttribute(fused_score_kernel,
                         cudaFuncAttributeMaxDynamicSharedMemorySize,
                         smem_bytes);
    fused_score_kernel<<<GRID_N, 256, smem_bytes>>>(q, k, qm, km, ls, out);
}